// round 3
// baseline (speedup 1.0000x reference)
#include <cuda_runtime.h>
#include <cuda_bf16.h>
#include <math.h>

typedef unsigned long long u64;

// Problem dims
#define B_ 64
#define T_ 512
#define D_ 512
#define U_ 1024
#define N4U 4096   // 4*U

#define KS 4            // K-splits in the recurrent GEMM
#define KSLEN (U_ / KS) // 256
#define NTILES 64       // col tiles of 64 (16 units x 4 gates)

// f32x2 helpers -----------------------------------------------------------------
__device__ __forceinline__ u64 dupf(float a) {
    u64 r;
    asm("mov.b64 %0, {%1, %1};" : "=l"(r) : "r"(__float_as_uint(a)));
    return r;
}
__device__ __forceinline__ void fma2(u64& acc, u64 a, u64 b) {
    asm("fma.rn.f32x2 %0, %1, %2, %0;" : "+l"(acc) : "l"(a), "l"(b));
}

// ---------------- scratch (device globals; no runtime allocation) -------------
__device__ float g_xg[(size_t)B_ * T_ * N4U];  // [B, T, 4U] : row (b*T + t)
__device__ float g_h0[B_ * U_];
__device__ float g_h1[B_ * U_];
__device__ float g_c [B_ * U_];
__device__ float g_zp[KS * NTILES * B_ * 64];  // [ks][ut][b][cc]
__device__ unsigned g_tk[128];                 // per-u-tile arrival tickets

// ---------------- init ----------------------------------------------------------
__global__ void lstm_init() {
    int i = blockIdx.x * blockDim.x + threadIdx.x;
    if (i < B_ * U_) { g_h0[i] = 0.f; g_c[i] = 0.f; }
    if (i < 128) g_tk[i] = 0u;
}

// ---------------- input projection GEMM (f32x2) ---------------------------------
// C[32768, 4096] = A[.,512] @ W[512, 4096]. 128x128 tile, BK=16, 256 thr, 8x8/thr.
#define PC_BM 128
#define PC_BN 128
#define PC_BK 16

__global__ __launch_bounds__(256, 2)
void lstm_xgemm(const float* __restrict__ A, const float* __restrict__ W) {
    __shared__ float As[PC_BK][PC_BM + 4];   // [k][m] transposed
    __shared__ float Bs[PC_BK][PC_BN + 4];   // [k][n]

    const int tid = threadIdx.x;
    const int tx = tid & 15;        // n
    const int ty = tid >> 4;        // m
    const int m0 = blockIdx.y * PC_BM;
    const int n0 = blockIdx.x * PC_BN;

    u64 acc[8][4];
    #pragma unroll
    for (int i = 0; i < 8; i++)
        #pragma unroll
        for (int j = 0; j < 4; j++) acc[i][j] = 0ull;

    for (int k0 = 0; k0 < D_; k0 += PC_BK) {
        #pragma unroll
        for (int l = 0; l < 2; l++) {
            int i = tid + l * 256;
            int m = i >> 2;
            int kq = (i & 3) << 2;
            float4 v = *(const float4*)(A + (size_t)(m0 + m) * D_ + k0 + kq);
            As[kq + 0][m] = v.x; As[kq + 1][m] = v.y;
            As[kq + 2][m] = v.z; As[kq + 3][m] = v.w;
        }
        #pragma unroll
        for (int l = 0; l < 2; l++) {
            int i = tid + l * 256;
            int kk = i >> 5;
            int nq = (i & 31) << 2;
            float4 v = *(const float4*)(W + (size_t)(k0 + kk) * N4U + n0 + nq);
            *(float4*)(&Bs[kk][nq]) = v;
        }
        __syncthreads();

        #pragma unroll
        for (int kk = 0; kk < PC_BK; kk++) {
            float4 aA = *(float4*)&As[kk][ty * 8];
            float4 aB = *(float4*)&As[kk][ty * 8 + 4];
            ulonglong2 w01 = *(ulonglong2*)&Bs[kk][tx * 8];
            ulonglong2 w23 = *(ulonglong2*)&Bs[kk][tx * 8 + 4];
            u64 wp[4] = {w01.x, w01.y, w23.x, w23.y};
            float av[8] = {aA.x, aA.y, aA.z, aA.w, aB.x, aB.y, aB.z, aB.w};
            #pragma unroll
            for (int i = 0; i < 8; i++) {
                u64 ad = dupf(av[i]);
                #pragma unroll
                for (int j = 0; j < 4; j++) fma2(acc[i][j], ad, wp[j]);
            }
        }
        __syncthreads();
    }

    #pragma unroll
    for (int i = 0; i < 8; i++) {
        float outv[8];
        #pragma unroll
        for (int j = 0; j < 4; j++) *(u64*)&outv[2 * j] = acc[i][j];
        size_t row = (size_t)(m0 + ty * 8 + i) * N4U + n0 + tx * 8;
        *(float4*)(&g_xg[row])     = *(float4*)&outv[0];
        *(float4*)(&g_xg[row + 4]) = *(float4*)&outv[4];
    }
}

// ---------------- fused recurrent step (f32x2, K-split + finisher) --------------
// grid = (KS=4, 64 tiles), block = 128 threads.
// Block tile: 64 batch x 64 cols (16 units x 4 gates), per-thread 4b x 8c.
#define ST_BK 32

__global__ __launch_bounds__(128)
void lstm_step(const float* __restrict__ W, int t) {
    const float* __restrict__ h_in = (t & 1) ? g_h1 : g_h0;
    float* __restrict__ h_out      = (t & 1) ? g_h0 : g_h1;

    __shared__ float Hs[ST_BK][68];   // [k][b]
    __shared__ float Ws[ST_BK][68];   // [k][cc]
    __shared__ unsigned sflag;

    const int tid = threadIdx.x;
    const int ks = blockIdx.x;        // 0..3
    const int ut = blockIdx.y;        // 0..63
    const int u0 = ut * 16;
    const int tr = tid >> 3;          // 0..15 -> 4 batch rows
    const int tc = tid & 7;           // 0..7  -> 8 cols

    u64 acc[4][4];                    // [batch i][col-pair j]
    #pragma unroll
    for (int i = 0; i < 4; i++)
        #pragma unroll
        for (int j = 0; j < 4; j++) acc[i][j] = 0ull;

    const int kbase = ks * KSLEN;
    for (int k0 = 0; k0 < KSLEN; k0 += ST_BK) {
        // H tile: 32k x 64b = 512 float4, 4/thread, transposed store
        #pragma unroll
        for (int l = 0; l < 4; l++) {
            int i = tid + l * 128;
            int b = i >> 3;
            int kq = (i & 7) << 2;
            float4 v = *(const float4*)(h_in + b * U_ + kbase + k0 + kq);
            Hs[kq + 0][b] = v.x; Hs[kq + 1][b] = v.y;
            Hs[kq + 2][b] = v.z; Hs[kq + 3][b] = v.w;
        }
        // W tile: 32k x 64cc = 512 float4, 4/thread
        #pragma unroll
        for (int l = 0; l < 4; l++) {
            int i = tid + l * 128;
            int kk = i >> 4;
            int nq = (i & 15) << 2;
            int col = ((nq >> 4) << 10) + u0 + (nq & 15);
            float4 v = *(const float4*)(W + (size_t)(kbase + k0 + kk) * N4U + col);
            *(float4*)(&Ws[kk][nq]) = v;
        }
        __syncthreads();

        #pragma unroll
        for (int kk = 0; kk < ST_BK; kk++) {
            float4 a4 = *(float4*)&Hs[kk][4 * tr];
            ulonglong2 w01 = *(ulonglong2*)&Ws[kk][8 * tc];
            ulonglong2 w23 = *(ulonglong2*)&Ws[kk][8 * tc + 4];
            u64 wp[4] = {w01.x, w01.y, w23.x, w23.y};
            float av[4] = {a4.x, a4.y, a4.z, a4.w};
            #pragma unroll
            for (int i = 0; i < 4; i++) {
                u64 ad = dupf(av[i]);
                #pragma unroll
                for (int j = 0; j < 4; j++) fma2(acc[i][j], ad, wp[j]);
            }
        }
        __syncthreads();
    }

    // write partial tile: g_zp[ks][ut][b][cc]
    {
        float* zp = g_zp + ((size_t)(ks * NTILES + ut) * B_) * 64;
        #pragma unroll
        for (int i = 0; i < 4; i++) {
            int b = 4 * tr + i;
            float outv[8];
            #pragma unroll
            for (int j = 0; j < 4; j++) *(u64*)&outv[2 * j] = acc[i][j];
            *(float4*)(zp + b * 64 + 8 * tc)     = *(float4*)&outv[0];
            *(float4*)(zp + b * 64 + 8 * tc + 4) = *(float4*)&outv[4];
        }
    }
    __threadfence();
    __syncthreads();
    if (tid == 0)
        sflag = (atomicAdd(&g_tk[ut], 1u) == (unsigned)(KS - 1)) ? 1u : 0u;
    __syncthreads();
    if (!sflag) return;
    if (tid == 0) g_tk[ut] = 0u;   // reset for next step (kernel-ordered)
    __threadfence();               // acquire partials

    // ---- finisher: 64b x 16u cells, 8 per thread; sum KS partials in fixed order
    for (int l = 0; l < 8; l++) {
        int e = tid + l * 128;
        int u = e & 15;
        int b = e >> 4;
        float z[4];
        #pragma unroll
        for (int g = 0; g < 4; g++) {
            float s = 0.f;
            #pragma unroll
            for (int p = 0; p < KS; p++)
                s += g_zp[((size_t)(p * NTILES + ut) * B_ + b) * 64 + g * 16 + u];
            z[g] = s + g_xg[((size_t)b * T_ + t) * N4U + (g << 10) + u0 + u];
        }
        float iv = 1.f / (1.f + __expf(-z[0]));
        float fv = 1.f / (1.f + __expf(-z[1]));
        float gv = tanhf(z[2]);
        float ov = 1.f / (1.f + __expf(-z[3]));
        int idx = b * U_ + u0 + u;
        float cv = fv * g_c[idx] + iv * gv;
        g_c[idx] = cv;
        h_out[idx] = ov * tanhf(cv);
    }
}

// ---------------- final copy ----------------------------------------------------
__global__ void lstm_copy_out(float* __restrict__ out) {
    int i = blockIdx.x * blockDim.x + threadIdx.x;
    if (i < B_ * U_) out[i] = g_h0[i];
}

// ---------------- launch --------------------------------------------------------
extern "C" void kernel_launch(void* const* d_in, const int* in_sizes, int n_in,
                              void* d_out, int out_size) {
    const float* x    = (const float*)d_in[0];   // [B, T, D]
    const float* kern = (const float*)d_in[1];   // [D, 4U]
    const float* rec  = (const float*)d_in[2];   // [U, 4U]
    float* out = (float*)d_out;                  // [B, U]

    lstm_init<<<(B_ * U_ + 255) / 256, 256>>>();

    dim3 pg(N4U / PC_BN, (B_ * T_) / PC_BM);     // (32, 256)
    lstm_xgemm<<<pg, 256>>>(x, kern);

    for (int t = 0; t < T_; t++) {
        dim3 sg(KS, NTILES);                     // 256 blocks x 128 thr
        lstm_step<<<sg, 128>>>(rec, t);
    }

    lstm_copy_out<<<(B_ * U_ + 255) / 256, 256>>>(out);
}

// round 4
// speedup vs baseline: 1.2601x; 1.2601x over previous
#include <cuda_runtime.h>
#include <cuda_bf16.h>
#include <math.h>

typedef unsigned long long u64;

// Problem dims
#define B_ 64
#define T_ 512
#define D_ 512
#define U_ 1024
#define N4U 4096   // 4*U

// Persistent-step decomposition
#define KS 8            // K splits (k-slice of 128 per block)
#define KSLEN 128
#define NT 64           // column tiles of 64 (16 units x 4 gates)
#define NBLK (KS * NT)  // 512 blocks, all co-resident

// f32x2 helpers -----------------------------------------------------------------
__device__ __forceinline__ u64 dupf(float a) {
    u64 r;
    asm("mov.b64 %0, {%1, %1};" : "=l"(r) : "r"(__float_as_uint(a)));
    return r;
}
__device__ __forceinline__ void fma2(u64& acc, u64 a, u64 b) {
    asm("fma.rn.f32x2 %0, %1, %2, %0;" : "+l"(acc) : "l"(a), "l"(b));
}

// ---------------- scratch (device globals) --------------------------------------
__device__ float g_xg[(size_t)B_ * T_ * N4U];  // [B, T, 4U]
__device__ float g_h[B_ * U_];                 // single h buffer (barrier-protected)
__device__ float g_zp[KS * NT * B_ * 64];      // [ks][ut][b][cc] partials
__device__ unsigned g_bar[2 * T_];             // per-step barrier counters

// ---------------- init ----------------------------------------------------------
__global__ void lstm_init() {
    int i = blockIdx.x * blockDim.x + threadIdx.x;
    if (i < B_ * U_) g_h[i] = 0.f;
    if (i < 2 * T_) g_bar[i] = 0u;
}

// ---------------- input projection GEMM (f32x2) ---------------------------------
#define PC_BM 128
#define PC_BN 128
#define PC_BK 16

__global__ __launch_bounds__(256, 2)
void lstm_xgemm(const float* __restrict__ A, const float* __restrict__ W) {
    __shared__ float As[PC_BK][PC_BM + 4];
    __shared__ float Bs[PC_BK][PC_BN + 4];

    const int tid = threadIdx.x;
    const int tx = tid & 15;
    const int ty = tid >> 4;
    const int m0 = blockIdx.y * PC_BM;
    const int n0 = blockIdx.x * PC_BN;

    u64 acc[8][4];
    #pragma unroll
    for (int i = 0; i < 8; i++)
        #pragma unroll
        for (int j = 0; j < 4; j++) acc[i][j] = 0ull;

    for (int k0 = 0; k0 < D_; k0 += PC_BK) {
        #pragma unroll
        for (int l = 0; l < 2; l++) {
            int i = tid + l * 256;
            int m = i >> 2;
            int kq = (i & 3) << 2;
            float4 v = *(const float4*)(A + (size_t)(m0 + m) * D_ + k0 + kq);
            As[kq + 0][m] = v.x; As[kq + 1][m] = v.y;
            As[kq + 2][m] = v.z; As[kq + 3][m] = v.w;
        }
        #pragma unroll
        for (int l = 0; l < 2; l++) {
            int i = tid + l * 256;
            int kk = i >> 5;
            int nq = (i & 31) << 2;
            float4 v = *(const float4*)(W + (size_t)(k0 + kk) * N4U + n0 + nq);
            *(float4*)(&Bs[kk][nq]) = v;
        }
        __syncthreads();

        #pragma unroll
        for (int kk = 0; kk < PC_BK; kk++) {
            float4 aA = *(float4*)&As[kk][ty * 8];
            float4 aB = *(float4*)&As[kk][ty * 8 + 4];
            ulonglong2 w01 = *(ulonglong2*)&Bs[kk][tx * 8];
            ulonglong2 w23 = *(ulonglong2*)&Bs[kk][tx * 8 + 4];
            u64 wp[4] = {w01.x, w01.y, w23.x, w23.y};
            float av[8] = {aA.x, aA.y, aA.z, aA.w, aB.x, aB.y, aB.z, aB.w};
            #pragma unroll
            for (int i = 0; i < 8; i++) {
                u64 ad = dupf(av[i]);
                #pragma unroll
                for (int j = 0; j < 4; j++) fma2(acc[i][j], ad, wp[j]);
            }
        }
        __syncthreads();
    }

    #pragma unroll
    for (int i = 0; i < 8; i++) {
        float outv[8];
        #pragma unroll
        for (int j = 0; j < 4; j++) *(u64*)&outv[2 * j] = acc[i][j];
        size_t row = (size_t)(m0 + ty * 8 + i) * N4U + n0 + tx * 8;
        *(float4*)(&g_xg[row])     = *(float4*)&outv[0];
        *(float4*)(&g_xg[row + 4]) = *(float4*)&outv[4];
    }
}

// ---------------- grid-wide barrier (per-step counters, no reuse) ---------------
__device__ __forceinline__ void gridbar(int bi) {
    __syncthreads();
    if (threadIdx.x == 0) {
        __threadfence();
        atomicAdd(&g_bar[bi], 1u);
        while (((volatile unsigned*)g_bar)[bi] < (unsigned)NBLK) __nanosleep(64);
    }
    __syncthreads();
    __threadfence();
}

// ---------------- persistent fused LSTM over all T steps ------------------------
// 512 blocks x 128 threads, all resident. Block (ks, ut):
//   mainloop: 64b x 64c partial GEMM over k in [ks*128, ks*128+128), W in smem.
//   finisher: 8 batches (ks*8..ks*8+8) x 16 units of tile ut; c in registers.
__global__ __launch_bounds__(128, 4)
void lstm_persist(const float* __restrict__ W, float* __restrict__ out) {
    extern __shared__ float sm[];
    float (*Ws)[68] = (float(*)[68])sm;              // [128][68]
    float (*Hs)[68] = (float(*)[68])(sm + 128 * 68); // [32][68]

    const int tid = threadIdx.x;
    const int bid = blockIdx.x;
    const int ks = bid & 7;
    const int ut = bid >> 3;
    const int u0 = ut * 16;
    const int kbase = ks * KSLEN;
    const int tr = tid >> 3;   // 0..15 -> 4 batch rows
    const int tc = tid & 7;    // 0..7  -> 8 cols

    // ---- load this block's W tile once: 128k x 64c ----
    #pragma unroll
    for (int l = 0; l < 16; l++) {
        int i = tid + l * 128;
        int kk = i >> 4;
        int nq = (i & 15) << 2;
        int col = ((nq >> 4) << 10) + u0 + (nq & 15);
        float4 v = *(const float4*)(W + (size_t)(kbase + kk) * N4U + col);
        *(float4*)(&Ws[kk][nq]) = v;
    }

    // ---- finisher cell ownership (fixed for whole run) ----
    const int fb = ks * 8 + (tid >> 4);   // batch 0..63
    const int fu = tid & 15;              // unit within tile
    const float* xgp = g_xg + (size_t)fb * T_ * N4U + u0 + fu;
    const int hidx = fb * U_ + u0 + fu;
    float c_reg = 0.f;

    for (int t = 0; t < T_; t++) {
        // ---- partial GEMM: acc[4 batch][4 col-pairs] ----
        u64 acc[4][4];
        #pragma unroll
        for (int i = 0; i < 4; i++)
            #pragma unroll
            for (int j = 0; j < 4; j++) acc[i][j] = 0ull;

        #pragma unroll
        for (int chunk = 0; chunk < 4; chunk++) {
            #pragma unroll
            for (int l = 0; l < 4; l++) {
                int i = tid + l * 128;
                int b = i >> 3;
                int kq = (i & 7) << 2;
                float4 v = *(const float4*)(g_h + b * U_ + kbase + chunk * 32 + kq);
                Hs[kq + 0][b] = v.x; Hs[kq + 1][b] = v.y;
                Hs[kq + 2][b] = v.z; Hs[kq + 3][b] = v.w;
            }
            __syncthreads();

            #pragma unroll
            for (int kk = 0; kk < 32; kk++) {
                float4 a4 = *(float4*)&Hs[kk][4 * tr];
                ulonglong2 w01 = *(ulonglong2*)&Ws[chunk * 32 + kk][8 * tc];
                ulonglong2 w23 = *(ulonglong2*)&Ws[chunk * 32 + kk][8 * tc + 4];
                u64 wp[4] = {w01.x, w01.y, w23.x, w23.y};
                float av[4] = {a4.x, a4.y, a4.z, a4.w};
                #pragma unroll
                for (int i = 0; i < 4; i++) {
                    u64 ad = dupf(av[i]);
                    #pragma unroll
                    for (int j = 0; j < 4; j++) fma2(acc[i][j], ad, wp[j]);
                }
            }
            __syncthreads();
        }

        // ---- write partial tile g_zp[ks][ut][b][cc] ----
        {
            float* zp = g_zp + ((size_t)(ks * NT + ut) * B_) * 64;
            #pragma unroll
            for (int i = 0; i < 4; i++) {
                int b = 4 * tr + i;
                float outv[8];
                #pragma unroll
                for (int j = 0; j < 4; j++) *(u64*)&outv[2 * j] = acc[i][j];
                *(float4*)(zp + b * 64 + 8 * tc)     = *(float4*)&outv[0];
                *(float4*)(zp + b * 64 + 8 * tc + 4) = *(float4*)&outv[4];
            }
        }

        gridbar(2 * t);

        // ---- finisher: one (b,u) cell per thread, fixed-order partial sum ----
        {
            float z[4];
            #pragma unroll
            for (int g = 0; g < 4; g++) {
                float s = 0.f;
                #pragma unroll
                for (int p = 0; p < KS; p++)
                    s += g_zp[((size_t)(p * NT + ut) * B_ + fb) * 64 + g * 16 + fu];
                z[g] = s + xgp[(size_t)t * N4U + (g << 10)];
            }
            float iv = 1.f / (1.f + __expf(-z[0]));
            float fv = 1.f / (1.f + __expf(-z[1]));
            float gv = tanhf(z[2]);
            float ov = 1.f / (1.f + __expf(-z[3]));
            c_reg = fv * c_reg + iv * gv;
            float hv = ov * tanhf(c_reg);
            g_h[hidx] = hv;
            if (t == T_ - 1) out[hidx] = hv;
        }

        gridbar(2 * t + 1);
    }
}

// ---------------- launch --------------------------------------------------------
extern "C" void kernel_launch(void* const* d_in, const int* in_sizes, int n_in,
                              void* d_out, int out_size) {
    const float* x    = (const float*)d_in[0];   // [B, T, D]
    const float* kern = (const float*)d_in[1];   // [D, 4U]
    const float* rec  = (const float*)d_in[2];   // [U, 4U]
    float* out = (float*)d_out;                  // [B, U]

    static int attr_done = 0;
    if (!attr_done) {
        cudaFuncSetAttribute(lstm_persist,
                             cudaFuncAttributePreferredSharedMemoryCarveout, 100);
        attr_done = 1;
    }

    lstm_init<<<(B_ * U_ + 255) / 256, 256>>>();

    dim3 pg(N4U / PC_BN, (B_ * T_) / PC_BM);     // (32, 256)
    lstm_xgemm<<<pg, 256>>>(x, kern);

    size_t smem = (128 * 68 + 32 * 68) * sizeof(float);  // 43.5 KB
    lstm_persist<<<NBLK, 128, smem>>>(rec, out);
}

// round 6
// speedup vs baseline: 1.3467x; 1.0688x over previous
#include <cuda_runtime.h>
#include <cuda_bf16.h>
#include <math.h>
#include <stdint.h>

typedef unsigned long long u64;

// Problem dims
#define B_ 64
#define T_ 512
#define D_ 512
#define U_ 1024
#define N4U 4096        // 4*U
#define BT_ (B_ * T_)   // 32768

// Persistent-step decomposition
#define KS 8
#define KSLEN 128
#define NT 64
#define NBLK (KS * NT)  // 512

// f32x2 helpers -------------------------------------------------------------
__device__ __forceinline__ u64 dupf(float a) {
    u64 r;
    asm("mov.b64 %0, {%1, %1};" : "=l"(r) : "r"(__float_as_uint(a)));
    return r;
}
__device__ __forceinline__ void fma2(u64& acc, u64 a, u64 b) {
    asm("fma.rn.f32x2 %0, %1, %2, %0;" : "+l"(acc) : "l"(a), "l"(b));
}

// mma.sync m16n8k16 bf16 (base PTX, works on compute_103) --------------------
#define MMA16816(c, a, b) \
    asm volatile("mma.sync.aligned.m16n8k16.row.col.f32.bf16.bf16.f32 " \
        "{%0,%1,%2,%3}, {%4,%5,%6,%7}, {%8,%9}, {%0,%1,%2,%3};" \
        : "+f"((c)[0]), "+f"((c)[1]), "+f"((c)[2]), "+f"((c)[3]) \
        : "r"((a)[0]), "r"((a)[1]), "r"((a)[2]), "r"((a)[3]), \
          "r"((b)[0]), "r"((b)[1]))

// ---------------- scratch (device globals) ----------------------------------
__device__ float g_xg[(size_t)BT_ * N4U];      // [B*T, 4U]
__device__ float g_h[B_ * U_];
__device__ float g_zp[KS * NT * B_ * 64];
__device__ unsigned g_bar[2 * T_];
__device__ __nv_bfloat16 g_xhi[(size_t)BT_ * D_];
__device__ __nv_bfloat16 g_xlo[(size_t)BT_ * D_];
__device__ __nv_bfloat16 g_whi[(size_t)N4U * D_];   // transposed: [n][k]
__device__ __nv_bfloat16 g_wlo[(size_t)N4U * D_];

// ---------------- init -------------------------------------------------------
__global__ void lstm_init() {
    int i = blockIdx.x * blockDim.x + threadIdx.x;
    if (i < B_ * U_) g_h[i] = 0.f;
    if (i < 2 * T_) g_bar[i] = 0u;
}

// ---------------- split-precision converters ---------------------------------
__global__ void conv_x(const float* __restrict__ x) {
    size_t i = (size_t)blockIdx.x * blockDim.x + threadIdx.x;
    if (i >= (size_t)BT_ * D_) return;
    float v = x[i];
    __nv_bfloat16 hi = __float2bfloat16(v);
    __nv_bfloat16 lo = __float2bfloat16(v - __bfloat162float(hi));
    g_xhi[i] = hi; g_xlo[i] = lo;
}
__global__ void conv_w(const float* __restrict__ W) {
    size_t i = (size_t)blockIdx.x * blockDim.x + threadIdx.x;  // over n*512+k
    if (i >= (size_t)N4U * D_) return;
    int n = (int)(i >> 9);
    int k = (int)(i & 511);
    float v = W[(size_t)k * N4U + n];
    __nv_bfloat16 hi = __float2bfloat16(v);
    __nv_bfloat16 lo = __float2bfloat16(v - __bfloat162float(hi));
    g_whi[i] = hi; g_wlo[i] = lo;
}

// ---------------- mma.sync xgemm: g_xg = x @ kernel (bf16x3 split) -------------
// CTA 128x128, BK=32, 256 thr (8 warps: 2m x 4n), warp tile 64x32.
// A = g_x{hi,lo} [BT][512] row-major; B = g_w{hi,lo} [4096][512] row-major (=W^T),
// which is exactly the .col operand for mma row.col.
__global__ __launch_bounds__(256, 1)
void lstm_xgemm_mma() {
    __shared__ __nv_bfloat16 Ahi[128][40];
    __shared__ __nv_bfloat16 Alo[128][40];
    __shared__ __nv_bfloat16 Bhi[128][40];
    __shared__ __nv_bfloat16 Blo[128][40];

    const int tid = threadIdx.x;
    const int wid = tid >> 5;
    const int lane = tid & 31;
    const int wm = wid & 1;       // 0..1
    const int wn = wid >> 1;      // 0..3
    const int m0 = blockIdx.y * 128;
    const int n0 = blockIdx.x * 128;
    const int lq = lane >> 2;         // lane/4
    const int lr = (lane & 3) << 1;   // 2*(lane%4)

    float acc[4][4][4];
    #pragma unroll
    for (int i = 0; i < 4; i++)
        #pragma unroll
        for (int j = 0; j < 4; j++)
            #pragma unroll
            for (int q = 0; q < 4; q++) acc[i][j][q] = 0.f;

    for (int kc = 0; kc < 16; kc++) {
        const int k0 = kc * 32;
        // load tiles: 128 rows x 32 bf16 = 1024 uint2 per tile, 4 per thread
        #pragma unroll
        for (int l = 0; l < 4; l++) {
            int i = tid + l * 256;
            int r = i >> 3;
            int c4 = (i & 7) << 2;
            size_t ga = (size_t)(m0 + r) * D_ + k0 + c4;
            *(uint2*)&Ahi[r][c4] = *(const uint2*)(g_xhi + ga);
            *(uint2*)&Alo[r][c4] = *(const uint2*)(g_xlo + ga);
            size_t gb = (size_t)(n0 + r) * D_ + k0 + c4;
            *(uint2*)&Bhi[r][c4] = *(const uint2*)(g_whi + gb);
            *(uint2*)&Blo[r][c4] = *(const uint2*)(g_wlo + gb);
        }
        __syncthreads();

        #pragma unroll
        for (int ksi = 0; ksi < 2; ksi++) {
            const int k16 = ksi * 16;
            uint32_t ahi[4][4], alo[4][4], bhi[4][2], blo[4][2];
            #pragma unroll
            for (int i = 0; i < 4; i++) {
                int r = wm * 64 + i * 16 + lq;
                ahi[i][0] = *(uint32_t*)&Ahi[r][k16 + lr];
                ahi[i][1] = *(uint32_t*)&Ahi[r + 8][k16 + lr];
                ahi[i][2] = *(uint32_t*)&Ahi[r][k16 + lr + 8];
                ahi[i][3] = *(uint32_t*)&Ahi[r + 8][k16 + lr + 8];
                alo[i][0] = *(uint32_t*)&Alo[r][k16 + lr];
                alo[i][1] = *(uint32_t*)&Alo[r + 8][k16 + lr];
                alo[i][2] = *(uint32_t*)&Alo[r][k16 + lr + 8];
                alo[i][3] = *(uint32_t*)&Alo[r + 8][k16 + lr + 8];
            }
            #pragma unroll
            for (int j = 0; j < 4; j++) {
                int r = wn * 32 + j * 8 + lq;
                bhi[j][0] = *(uint32_t*)&Bhi[r][k16 + lr];
                bhi[j][1] = *(uint32_t*)&Bhi[r][k16 + lr + 8];
                blo[j][0] = *(uint32_t*)&Blo[r][k16 + lr];
                blo[j][1] = *(uint32_t*)&Blo[r][k16 + lr + 8];
            }
            #pragma unroll
            for (int i = 0; i < 4; i++)
                #pragma unroll
                for (int j = 0; j < 4; j++) {
                    MMA16816(acc[i][j], ahi[i], bhi[j]);
                    MMA16816(acc[i][j], ahi[i], blo[j]);
                    MMA16816(acc[i][j], alo[i], bhi[j]);
                }
        }
        __syncthreads();
    }

    // epilogue: c frag (m=lq(+8), n=lr(+1))
    #pragma unroll
    for (int i = 0; i < 4; i++) {
        int row = m0 + wm * 64 + i * 16 + lq;
        #pragma unroll
        for (int j = 0; j < 4; j++) {
            int col = n0 + wn * 32 + j * 8 + lr;
            *(float2*)&g_xg[(size_t)row * N4U + col] =
                make_float2(acc[i][j][0], acc[i][j][1]);
            *(float2*)&g_xg[(size_t)(row + 8) * N4U + col] =
                make_float2(acc[i][j][2], acc[i][j][3]);
        }
    }
}

// ---------------- grid-wide barrier -------------------------------------------
__device__ __forceinline__ void gridbar(int bi) {
    __syncthreads();
    if (threadIdx.x == 0) {
        __threadfence();
        atomicAdd(&g_bar[bi], 1u);
        while (((volatile unsigned*)g_bar)[bi] < (unsigned)NBLK) __nanosleep(64);
    }
    __syncthreads();
    __threadfence();
}

// ---------------- persistent fused LSTM over all T steps ----------------------
__global__ __launch_bounds__(128, 4)
void lstm_persist(const float* __restrict__ W, float* __restrict__ out) {
    extern __shared__ float sm[];
    float (*Ws)[68] = (float(*)[68])sm;
    float (*Hs)[68] = (float(*)[68])(sm + 128 * 68);

    const int tid = threadIdx.x;
    const int bid = blockIdx.x;
    const int ks = bid & 7;
    const int ut = bid >> 3;
    const int u0 = ut * 16;
    const int kbase = ks * KSLEN;
    const int tr = tid >> 3;
    const int tc = tid & 7;

    #pragma unroll
    for (int l = 0; l < 16; l++) {
        int i = tid + l * 128;
        int kk = i >> 4;
        int nq = (i & 15) << 2;
        int col = ((nq >> 4) << 10) + u0 + (nq & 15);
        float4 v = *(const float4*)(W + (size_t)(kbase + kk) * N4U + col);
        *(float4*)(&Ws[kk][nq]) = v;
    }

    const int fb = ks * 8 + (tid >> 4);
    const int fu = tid & 15;
    const float* xgp = g_xg + (size_t)fb * T_ * N4U + u0 + fu;
    const int hidx = fb * U_ + u0 + fu;
    float c_reg = 0.f;

    for (int t = 0; t < T_; t++) {
        u64 acc[4][4];
        #pragma unroll
        for (int i = 0; i < 4; i++)
            #pragma unroll
            for (int j = 0; j < 4; j++) acc[i][j] = 0ull;

        #pragma unroll
        for (int chunk = 0; chunk < 4; chunk++) {
            #pragma unroll
            for (int l = 0; l < 4; l++) {
                int i = tid + l * 128;
                int b = i >> 3;
                int kq = (i & 7) << 2;
                float4 v = *(const float4*)(g_h + b * U_ + kbase + chunk * 32 + kq);
                Hs[kq + 0][b] = v.x; Hs[kq + 1][b] = v.y;
                Hs[kq + 2][b] = v.z; Hs[kq + 3][b] = v.w;
            }
            __syncthreads();

            #pragma unroll
            for (int kk = 0; kk < 32; kk++) {
                float4 a4 = *(float4*)&Hs[kk][4 * tr];
                ulonglong2 w01 = *(ulonglong2*)&Ws[chunk * 32 + kk][8 * tc];
                ulonglong2 w23 = *(ulonglong2*)&Ws[chunk * 32 + kk][8 * tc + 4];
                u64 wp[4] = {w01.x, w01.y, w23.x, w23.y};
                float av[4] = {a4.x, a4.y, a4.z, a4.w};
                #pragma unroll
                for (int i = 0; i < 4; i++) {
                    u64 ad = dupf(av[i]);
                    #pragma unroll
                    for (int j = 0; j < 4; j++) fma2(acc[i][j], ad, wp[j]);
                }
            }
            __syncthreads();
        }

        {
            float* zp = g_zp + ((size_t)(ks * NT + ut) * B_) * 64;
            #pragma unroll
            for (int i = 0; i < 4; i++) {
                int b = 4 * tr + i;
                float outv[8];
                #pragma unroll
                for (int j = 0; j < 4; j++) *(u64*)&outv[2 * j] = acc[i][j];
                *(float4*)(zp + b * 64 + 8 * tc)     = *(float4*)&outv[0];
                *(float4*)(zp + b * 64 + 8 * tc + 4) = *(float4*)&outv[4];
            }
        }

        gridbar(2 * t);

        {
            float z[4];
            #pragma unroll
            for (int g = 0; g < 4; g++) {
                float s = 0.f;
                #pragma unroll
                for (int p = 0; p < KS; p++)
                    s += g_zp[((size_t)(p * NT + ut) * B_ + fb) * 64 + g * 16 + fu];
                z[g] = s + xgp[(size_t)t * N4U + (g << 10)];
            }
            float iv = 1.f / (1.f + __expf(-z[0]));
            float fv = 1.f / (1.f + __expf(-z[1]));
            float gv = tanhf(z[2]);
            float ov = 1.f / (1.f + __expf(-z[3]));
            c_reg = fv * c_reg + iv * gv;
            float hv = ov * tanhf(c_reg);
            g_h[hidx] = hv;
            if (t == T_ - 1) out[hidx] = hv;
        }

        gridbar(2 * t + 1);
    }
}

// ---------------- launch --------------------------------------------------------
extern "C" void kernel_launch(void* const* d_in, const int* in_sizes, int n_in,
                              void* d_out, int out_size) {
    const float* x    = (const float*)d_in[0];
    const float* kern = (const float*)d_in[1];
    const float* rec  = (const float*)d_in[2];
    float* out = (float*)d_out;

    static int attr_done = 0;
    if (!attr_done) {
        cudaFuncSetAttribute(lstm_persist,
                             cudaFuncAttributePreferredSharedMemoryCarveout, 100);
        attr_done = 1;
    }

    lstm_init<<<(B_ * U_ + 255) / 256, 256>>>();

    conv_x<<<(int)(((size_t)BT_ * D_ + 255) / 256), 256>>>(x);
    conv_w<<<(int)(((size_t)N4U * D_ + 255) / 256), 256>>>(kern);

    dim3 xg(N4U / 128, BT_ / 128);   // (32, 256)
    lstm_xgemm_mma<<<xg, 256>>>();

    size_t smem = (128 * 68 + 32 * 68) * sizeof(float);
    lstm_persist<<<NBLK, 128, smem>>>(rec, out);
}

// round 7
// speedup vs baseline: 2.1930x; 1.6284x over previous
#include <cuda_runtime.h>
#include <cuda_bf16.h>
#include <math.h>
#include <stdint.h>

typedef unsigned long long u64;

// Problem dims
#define B_ 64
#define T_ 512
#define D_ 512
#define U_ 1024
#define N4U 4096        // 4*U
#define BT_ (B_ * T_)   // 32768

#define NB2 128         // persistent blocks (1 per SM)
#define WROW 1032       // smem W row stride in bf16 elems (bank-conflict-free)

// mma.sync m16n8k16 bf16 (base PTX, works on compute_103) --------------------
#define MMA16816(c, a, b) \
    asm volatile("mma.sync.aligned.m16n8k16.row.col.f32.bf16.bf16.f32 " \
        "{%0,%1,%2,%3}, {%4,%5,%6,%7}, {%8,%9}, {%0,%1,%2,%3};" \
        : "+f"((c)[0]), "+f"((c)[1]), "+f"((c)[2]), "+f"((c)[3]) \
        : "r"((a)[0]), "r"((a)[1]), "r"((a)[2]), "r"((a)[3]), \
          "r"((b)[0]), "r"((b)[1]))

// ---------------- scratch (device globals) ----------------------------------
__device__ float g_xg[(size_t)BT_ * N4U];             // [B*T, 4U]
__device__ __nv_bfloat16 g_hhi[2][B_ * U_];           // h split, double-buffered
__device__ __nv_bfloat16 g_hlo[2][B_ * U_];
__device__ unsigned g_bar2[T_];
__device__ __nv_bfloat16 g_xhi[(size_t)BT_ * D_];
__device__ __nv_bfloat16 g_xlo[(size_t)BT_ * D_];
__device__ __nv_bfloat16 g_whi[(size_t)N4U * D_];     // x-proj W^T: [n][k]
__device__ __nv_bfloat16 g_wlo[(size_t)N4U * D_];

// ---------------- init -------------------------------------------------------
__global__ void lstm_init() {
    int i = blockIdx.x * blockDim.x + threadIdx.x;
    if (i < B_ * U_) {
        g_hhi[0][i] = __float2bfloat16(0.f);
        g_hlo[0][i] = __float2bfloat16(0.f);
    }
    if (i < T_) g_bar2[i] = 0u;
}

// ---------------- split-precision converters ---------------------------------
__global__ void conv_x(const float* __restrict__ x) {
    size_t i = (size_t)blockIdx.x * blockDim.x + threadIdx.x;
    if (i >= (size_t)BT_ * D_) return;
    float v = x[i];
    __nv_bfloat16 hi = __float2bfloat16(v);
    __nv_bfloat16 lo = __float2bfloat16(v - __bfloat162float(hi));
    g_xhi[i] = hi; g_xlo[i] = lo;
}
__global__ void conv_w(const float* __restrict__ W) {
    size_t i = (size_t)blockIdx.x * blockDim.x + threadIdx.x;  // over n*512+k
    if (i >= (size_t)N4U * D_) return;
    int n = (int)(i >> 9);
    int k = (int)(i & 511);
    float v = W[(size_t)k * N4U + n];
    __nv_bfloat16 hi = __float2bfloat16(v);
    __nv_bfloat16 lo = __float2bfloat16(v - __bfloat162float(hi));
    g_whi[i] = hi; g_wlo[i] = lo;
}

// ---------------- mma.sync xgemm: g_xg = x @ kernel (bf16x3 split) -------------
__global__ __launch_bounds__(256, 1)
void lstm_xgemm_mma() {
    __shared__ __nv_bfloat16 Ahi[128][40];
    __shared__ __nv_bfloat16 Alo[128][40];
    __shared__ __nv_bfloat16 Bhi[128][40];
    __shared__ __nv_bfloat16 Blo[128][40];

    const int tid = threadIdx.x;
    const int wid = tid >> 5;
    const int lane = tid & 31;
    const int wm = wid & 1;
    const int wn = wid >> 1;
    const int m0 = blockIdx.y * 128;
    const int n0 = blockIdx.x * 128;
    const int lq = lane >> 2;
    const int lr = (lane & 3) << 1;

    float acc[4][4][4];
    #pragma unroll
    for (int i = 0; i < 4; i++)
        #pragma unroll
        for (int j = 0; j < 4; j++)
            #pragma unroll
            for (int q = 0; q < 4; q++) acc[i][j][q] = 0.f;

    for (int kc = 0; kc < 16; kc++) {
        const int k0 = kc * 32;
        #pragma unroll
        for (int l = 0; l < 4; l++) {
            int i = tid + l * 256;
            int r = i >> 3;
            int c4 = (i & 7) << 2;
            size_t ga = (size_t)(m0 + r) * D_ + k0 + c4;
            *(uint2*)&Ahi[r][c4] = *(const uint2*)(g_xhi + ga);
            *(uint2*)&Alo[r][c4] = *(const uint2*)(g_xlo + ga);
            size_t gb = (size_t)(n0 + r) * D_ + k0 + c4;
            *(uint2*)&Bhi[r][c4] = *(const uint2*)(g_whi + gb);
            *(uint2*)&Blo[r][c4] = *(const uint2*)(g_wlo + gb);
        }
        __syncthreads();

        #pragma unroll
        for (int ksi = 0; ksi < 2; ksi++) {
            const int k16 = ksi * 16;
            uint32_t ahi[4][4], alo[4][4], bhi[4][2], blo[4][2];
            #pragma unroll
            for (int i = 0; i < 4; i++) {
                int r = wm * 64 + i * 16 + lq;
                ahi[i][0] = *(uint32_t*)&Ahi[r][k16 + lr];
                ahi[i][1] = *(uint32_t*)&Ahi[r + 8][k16 + lr];
                ahi[i][2] = *(uint32_t*)&Ahi[r][k16 + lr + 8];
                ahi[i][3] = *(uint32_t*)&Ahi[r + 8][k16 + lr + 8];
                alo[i][0] = *(uint32_t*)&Alo[r][k16 + lr];
                alo[i][1] = *(uint32_t*)&Alo[r + 8][k16 + lr];
                alo[i][2] = *(uint32_t*)&Alo[r][k16 + lr + 8];
                alo[i][3] = *(uint32_t*)&Alo[r + 8][k16 + lr + 8];
            }
            #pragma unroll
            for (int j = 0; j < 4; j++) {
                int r = wn * 32 + j * 8 + lq;
                bhi[j][0] = *(uint32_t*)&Bhi[r][k16 + lr];
                bhi[j][1] = *(uint32_t*)&Bhi[r][k16 + lr + 8];
                blo[j][0] = *(uint32_t*)&Blo[r][k16 + lr];
                blo[j][1] = *(uint32_t*)&Blo[r][k16 + lr + 8];
            }
            #pragma unroll
            for (int i = 0; i < 4; i++)
                #pragma unroll
                for (int j = 0; j < 4; j++) {
                    MMA16816(acc[i][j], ahi[i], bhi[j]);
                    MMA16816(acc[i][j], ahi[i], blo[j]);
                    MMA16816(acc[i][j], alo[i], bhi[j]);
                }
        }
        __syncthreads();
    }

    #pragma unroll
    for (int i = 0; i < 4; i++) {
        int row = m0 + wm * 64 + i * 16 + lq;
        #pragma unroll
        for (int j = 0; j < 4; j++) {
            int col = n0 + wn * 32 + j * 8 + lr;
            *(float2*)&g_xg[(size_t)row * N4U + col] =
                make_float2(acc[i][j][0], acc[i][j][1]);
            *(float2*)&g_xg[(size_t)(row + 8) * N4U + col] =
                make_float2(acc[i][j][2], acc[i][j][3]);
        }
    }
}

// ---------------- grid-wide barrier (128 blocks) -------------------------------
__device__ __forceinline__ void gridbar2(int t) {
    __syncthreads();
    if (threadIdx.x == 0) {
        __threadfence();
        atomicAdd(&g_bar2[t], 1u);
        while (((volatile unsigned*)g_bar2)[t] < (unsigned)NB2) __nanosleep(32);
    }
    __syncthreads();
    __threadfence();
}

// ---------------- persistent recurrent LSTM (mma.sync bf16x3) ------------------
// 128 blocks x 256 thr. Block owns 8 units (32 z-cols), full K=1024.
// W tile split to bf16 hi/lo in smem once. h double-buffered bf16 hi/lo in gmem.
// Warps: wm = warp&3 (m16-tile of batch), kh = warp>>2 (K-half of 512).
__global__ __launch_bounds__(256)
void lstm_persist_mma(const float* __restrict__ W, float* __restrict__ out) {
    extern __shared__ char sm2[];
    __nv_bfloat16* Whi = (__nv_bfloat16*)sm2;        // [32][WROW]
    __nv_bfloat16* Wlo = Whi + 32 * WROW;
    float* Zs = (float*)(Wlo + 32 * WROW);           // [64][33]

    const int tid = threadIdx.x;
    const int wid = tid >> 5;
    const int lane = tid & 31;
    const int wm = wid & 3;
    const int kh = wid >> 2;
    const int lq = lane >> 2;
    const int lr = (lane & 3) << 1;
    const int u0 = blockIdx.x * 8;

    // ---- load + split W tile into smem (once): 32 cols x 1024 k ----
    for (int l = 0; l < 128; l++) {
        int idx = tid + l * 256;
        int cc = idx & 31;
        int k = idx >> 5;
        int col = ((cc >> 3) << 10) + u0 + (cc & 7);
        float v = W[(size_t)k * N4U + col];
        __nv_bfloat16 hi = __float2bfloat16(v);
        Whi[cc * WROW + k] = hi;
        Wlo[cc * WROW + k] = __float2bfloat16(v - __bfloat162float(hi));
    }

    // finisher cells: 2 per thread
    const int b0c = tid >> 3,           u0c = tid & 7;
    const int b1c = (tid + 256) >> 3,   u1c = tid & 7;
    float c0 = 0.f, c1 = 0.f;

    const int ra = wm * 16 + lq;

    for (int t = 0; t < T_; t++) {
        gridbar2(t);   // all h[t&1] writes visible; also covers W-load at t=0

        const __nv_bfloat16* __restrict__ hh = g_hhi[t & 1];
        const __nv_bfloat16* __restrict__ hl = g_hlo[t & 1];

        float acc[4][4];
        #pragma unroll
        for (int j = 0; j < 4; j++)
            #pragma unroll
            for (int q = 0; q < 4; q++) acc[j][q] = 0.f;

        const int kbase = kh * 512;
        #pragma unroll 4
        for (int s = 0; s < 32; s++) {
            const int k = kbase + s * 16;
            const __nv_bfloat16* p0 = hh + ra * U_ + k;
            const __nv_bfloat16* p1 = hh + (ra + 8) * U_ + k;
            const __nv_bfloat16* q0 = hl + ra * U_ + k;
            const __nv_bfloat16* q1 = hl + (ra + 8) * U_ + k;
            uint32_t ahi[4], alo[4];
            ahi[0] = *(const uint32_t*)(p0 + lr);
            ahi[1] = *(const uint32_t*)(p1 + lr);
            ahi[2] = *(const uint32_t*)(p0 + 8 + lr);
            ahi[3] = *(const uint32_t*)(p1 + 8 + lr);
            alo[0] = *(const uint32_t*)(q0 + lr);
            alo[1] = *(const uint32_t*)(q1 + lr);
            alo[2] = *(const uint32_t*)(q0 + 8 + lr);
            alo[3] = *(const uint32_t*)(q1 + 8 + lr);
            #pragma unroll
            for (int j = 0; j < 4; j++) {
                const __nv_bfloat16* wh = Whi + (j * 8 + lq) * WROW + k;
                const __nv_bfloat16* wl = Wlo + (j * 8 + lq) * WROW + k;
                uint32_t bh[2], bl[2];
                bh[0] = *(const uint32_t*)(wh + lr);
                bh[1] = *(const uint32_t*)(wh + 8 + lr);
                bl[0] = *(const uint32_t*)(wl + lr);
                bl[1] = *(const uint32_t*)(wl + 8 + lr);
                MMA16816(acc[j], ahi, bh);
                MMA16816(acc[j], ahi, bl);
                MMA16816(acc[j], alo, bh);
            }
        }

        // ---- K-half reduction in fixed order: kh=1 stores, kh=0 adds ----
        if (kh == 1) {
            #pragma unroll
            for (int j = 0; j < 4; j++) {
                int cgl = j * 8 + lr;
                Zs[ra * 33 + cgl]           = acc[j][0];
                Zs[ra * 33 + cgl + 1]       = acc[j][1];
                Zs[(ra + 8) * 33 + cgl]     = acc[j][2];
                Zs[(ra + 8) * 33 + cgl + 1] = acc[j][3];
            }
        }
        __syncthreads();
        if (kh == 0) {
            #pragma unroll
            for (int j = 0; j < 4; j++) {
                int cgl = j * 8 + lr;
                Zs[ra * 33 + cgl]           += acc[j][0];
                Zs[ra * 33 + cgl + 1]       += acc[j][1];
                Zs[(ra + 8) * 33 + cgl]     += acc[j][2];
                Zs[(ra + 8) * 33 + cgl + 1] += acc[j][3];
            }
        }
        __syncthreads();

        // ---- finisher: 2 cells per thread ----
        __nv_bfloat16* __restrict__ nhh = g_hhi[(t + 1) & 1];
        __nv_bfloat16* __restrict__ nhl = g_hlo[(t + 1) & 1];
        #pragma unroll
        for (int cell = 0; cell < 2; cell++) {
            const int b = cell ? b1c : b0c;
            const int ul = cell ? u1c : u0c;
            float z[4];
            #pragma unroll
            for (int g = 0; g < 4; g++)
                z[g] = Zs[b * 33 + g * 8 + ul]
                     + g_xg[((size_t)b * T_ + t) * N4U + (g << 10) + u0 + ul];
            float iv = 1.f / (1.f + __expf(-z[0]));
            float fv = 1.f / (1.f + __expf(-z[1]));
            float gv = tanhf(z[2]);
            float ov = 1.f / (1.f + __expf(-z[3]));
            float cv = fv * (cell ? c1 : c0) + iv * gv;
            if (cell) c1 = cv; else c0 = cv;
            float hv = ov * tanhf(cv);
            int hix = b * U_ + u0 + ul;
            __nv_bfloat16 hi = __float2bfloat16(hv);
            nhh[hix] = hi;
            nhl[hix] = __float2bfloat16(hv - __bfloat162float(hi));
            if (t == T_ - 1) out[hix] = hv;
        }
        // next iteration's gridbar2 orders Zs reuse and h visibility
    }
}

// ---------------- launch --------------------------------------------------------
extern "C" void kernel_launch(void* const* d_in, const int* in_sizes, int n_in,
                              void* d_out, int out_size) {
    const float* x    = (const float*)d_in[0];
    const float* kern = (const float*)d_in[1];
    const float* rec  = (const float*)d_in[2];
    float* out = (float*)d_out;

    static int attr_done = 0;
    const size_t smem2 = (size_t)(32 * WROW * 2) * sizeof(__nv_bfloat16)
                       + (size_t)(64 * 33) * sizeof(float);   // ~141 KB
    if (!attr_done) {
        cudaFuncSetAttribute(lstm_persist_mma,
                             cudaFuncAttributeMaxDynamicSharedMemorySize, (int)smem2);
        cudaFuncSetAttribute(lstm_persist_mma,
                             cudaFuncAttributePreferredSharedMemoryCarveout, 100);
        attr_done = 1;
    }

    lstm_init<<<(B_ * U_ + 255) / 256, 256>>>();

    conv_x<<<(int)(((size_t)BT_ * D_ + 255) / 256), 256>>>(x);
    conv_w<<<(int)(((size_t)N4U * D_ + 255) / 256), 256>>>(kern);

    dim3 xg(N4U / 128, BT_ / 128);   // (32, 256)
    lstm_xgemm_mma<<<xg, 256>>>();

    lstm_persist_mma<<<NB2, 256, smem2>>>(rec, out);
}

// round 8
// speedup vs baseline: 2.3181x; 1.0570x over previous
#include <cuda_runtime.h>
#include <cuda_bf16.h>
#include <math.h>
#include <stdint.h>

typedef unsigned long long u64;

// Problem dims
#define B_ 64
#define T_ 512
#define D_ 512
#define U_ 1024
#define N4U 4096        // 4*U
#define BT_ (B_ * T_)   // 32768

#define NB2 128         // persistent blocks (1 per SM)
#define WROW 1032       // smem W row stride in bf16 elems (bank-conflict-free)

// mma.sync m16n8k16 bf16 (base PTX, works on compute_103) --------------------
#define MMA16816(c, a, b) \
    asm volatile("mma.sync.aligned.m16n8k16.row.col.f32.bf16.bf16.f32 " \
        "{%0,%1,%2,%3}, {%4,%5,%6,%7}, {%8,%9}, {%0,%1,%2,%3};" \
        : "+f"((c)[0]), "+f"((c)[1]), "+f"((c)[2]), "+f"((c)[3]) \
        : "r"((a)[0]), "r"((a)[1]), "r"((a)[2]), "r"((a)[3]), \
          "r"((b)[0]), "r"((b)[1]))

// ---------------- scratch (device globals) ----------------------------------
__device__ float g_xg[(size_t)BT_ * N4U];             // [B*T, 4U]
__device__ __nv_bfloat16 g_hhi[2][B_ * U_];           // h split, double-buffered
__device__ __nv_bfloat16 g_hlo[2][B_ * U_];
__device__ unsigned g_bar2[T_];
__device__ __nv_bfloat16 g_xhi[(size_t)BT_ * D_];
__device__ __nv_bfloat16 g_xlo[(size_t)BT_ * D_];
__device__ __nv_bfloat16 g_whi[(size_t)N4U * D_];     // x-proj W^T: [n][k]
__device__ __nv_bfloat16 g_wlo[(size_t)N4U * D_];

// ---------------- init -------------------------------------------------------
__global__ void lstm_init() {
    int i = blockIdx.x * blockDim.x + threadIdx.x;
    if (i < B_ * U_) {
        g_hhi[0][i] = __float2bfloat16(0.f);
        g_hlo[0][i] = __float2bfloat16(0.f);
    }
    if (i < T_) g_bar2[i] = 0u;
}

// ---------------- split-precision converters ---------------------------------
__global__ void conv_x(const float* __restrict__ x) {
    size_t i = (size_t)blockIdx.x * blockDim.x + threadIdx.x;
    if (i >= (size_t)BT_ * D_) return;
    float v = x[i];
    __nv_bfloat16 hi = __float2bfloat16(v);
    __nv_bfloat16 lo = __float2bfloat16(v - __bfloat162float(hi));
    g_xhi[i] = hi; g_xlo[i] = lo;
}
__global__ void conv_w(const float* __restrict__ W) {
    size_t i = (size_t)blockIdx.x * blockDim.x + threadIdx.x;  // over n*512+k
    if (i >= (size_t)N4U * D_) return;
    int n = (int)(i >> 9);
    int k = (int)(i & 511);
    float v = W[(size_t)k * N4U + n];
    __nv_bfloat16 hi = __float2bfloat16(v);
    __nv_bfloat16 lo = __float2bfloat16(v - __bfloat162float(hi));
    g_whi[i] = hi; g_wlo[i] = lo;
}

// ---------------- mma.sync xgemm: g_xg = x @ kernel (bf16x3 split) -------------
__global__ __launch_bounds__(256, 1)
void lstm_xgemm_mma() {
    __shared__ __nv_bfloat16 Ahi[128][40];
    __shared__ __nv_bfloat16 Alo[128][40];
    __shared__ __nv_bfloat16 Bhi[128][40];
    __shared__ __nv_bfloat16 Blo[128][40];

    const int tid = threadIdx.x;
    const int wid = tid >> 5;
    const int lane = tid & 31;
    const int wm = wid & 1;
    const int wn = wid >> 1;
    const int m0 = blockIdx.y * 128;
    const int n0 = blockIdx.x * 128;
    const int lq = lane >> 2;
    const int lr = (lane & 3) << 1;

    float acc[4][4][4];
    #pragma unroll
    for (int i = 0; i < 4; i++)
        #pragma unroll
        for (int j = 0; j < 4; j++)
            #pragma unroll
            for (int q = 0; q < 4; q++) acc[i][j][q] = 0.f;

    for (int kc = 0; kc < 16; kc++) {
        const int k0 = kc * 32;
        #pragma unroll
        for (int l = 0; l < 4; l++) {
            int i = tid + l * 256;
            int r = i >> 3;
            int c4 = (i & 7) << 2;
            size_t ga = (size_t)(m0 + r) * D_ + k0 + c4;
            *(uint2*)&Ahi[r][c4] = *(const uint2*)(g_xhi + ga);
            *(uint2*)&Alo[r][c4] = *(const uint2*)(g_xlo + ga);
            size_t gb = (size_t)(n0 + r) * D_ + k0 + c4;
            *(uint2*)&Bhi[r][c4] = *(const uint2*)(g_whi + gb);
            *(uint2*)&Blo[r][c4] = *(const uint2*)(g_wlo + gb);
        }
        __syncthreads();

        #pragma unroll
        for (int ksi = 0; ksi < 2; ksi++) {
            const int k16 = ksi * 16;
            uint32_t ahi[4][4], alo[4][4], bhi[4][2], blo[4][2];
            #pragma unroll
            for (int i = 0; i < 4; i++) {
                int r = wm * 64 + i * 16 + lq;
                ahi[i][0] = *(uint32_t*)&Ahi[r][k16 + lr];
                ahi[i][1] = *(uint32_t*)&Ahi[r + 8][k16 + lr];
                ahi[i][2] = *(uint32_t*)&Ahi[r][k16 + lr + 8];
                ahi[i][3] = *(uint32_t*)&Ahi[r + 8][k16 + lr + 8];
                alo[i][0] = *(uint32_t*)&Alo[r][k16 + lr];
                alo[i][1] = *(uint32_t*)&Alo[r + 8][k16 + lr];
                alo[i][2] = *(uint32_t*)&Alo[r][k16 + lr + 8];
                alo[i][3] = *(uint32_t*)&Alo[r + 8][k16 + lr + 8];
            }
            #pragma unroll
            for (int j = 0; j < 4; j++) {
                int r = wn * 32 + j * 8 + lq;
                bhi[j][0] = *(uint32_t*)&Bhi[r][k16 + lr];
                bhi[j][1] = *(uint32_t*)&Bhi[r][k16 + lr + 8];
                blo[j][0] = *(uint32_t*)&Blo[r][k16 + lr];
                blo[j][1] = *(uint32_t*)&Blo[r][k16 + lr + 8];
            }
            #pragma unroll
            for (int i = 0; i < 4; i++)
                #pragma unroll
                for (int j = 0; j < 4; j++) {
                    MMA16816(acc[i][j], ahi[i], bhi[j]);
                    MMA16816(acc[i][j], ahi[i], blo[j]);
                    MMA16816(acc[i][j], alo[i], bhi[j]);
                }
        }
        __syncthreads();
    }

    #pragma unroll
    for (int i = 0; i < 4; i++) {
        int row = m0 + wm * 64 + i * 16 + lq;
        #pragma unroll
        for (int j = 0; j < 4; j++) {
            int col = n0 + wn * 32 + j * 8 + lr;
            *(float2*)&g_xg[(size_t)row * N4U + col] =
                make_float2(acc[i][j][0], acc[i][j][1]);
            *(float2*)&g_xg[(size_t)(row + 8) * N4U + col] =
                make_float2(acc[i][j][2], acc[i][j][3]);
        }
    }
}

// ---------------- grid-wide barrier (128 blocks) -------------------------------
__device__ __forceinline__ void gridbar2(int t) {
    __syncthreads();
    if (threadIdx.x == 0) {
        __threadfence();
        atomicAdd(&g_bar2[t], 1u);
        while (((volatile unsigned*)g_bar2)[t] < (unsigned)NB2) __nanosleep(32);
    }
    __syncthreads();
    __threadfence();
}

// ---------------- persistent recurrent LSTM (mma.sync bf16x3, 512 thr) ---------
// 128 blocks x 512 thr (16 warps). Block owns 8 units (32 z-cols), K=1024.
// Warps: wm = wid&3 (batch m16-tile), kq = wid>>2 (K-quarter of 256).
// Zs[kq] slices reduced by finisher in fixed order -> deterministic.
__global__ __launch_bounds__(512)
void lstm_persist_mma(const float* __restrict__ W, float* __restrict__ out) {
    extern __shared__ char sm2[];
    __nv_bfloat16* Whi = (__nv_bfloat16*)sm2;        // [32][WROW]
    __nv_bfloat16* Wlo = Whi + 32 * WROW;
    float* Zs = (float*)(Wlo + 32 * WROW);           // [4][64][33]

    const int tid = threadIdx.x;
    const int wid = tid >> 5;
    const int lane = tid & 31;
    const int wm = wid & 3;
    const int kq = wid >> 2;          // 0..3
    const int lq = lane >> 2;
    const int lr = (lane & 3) << 1;
    const int u0 = blockIdx.x * 8;

    // ---- load + split W tile into smem (once): 32 cols x 1024 k ----
    for (int l = 0; l < 64; l++) {
        int idx = tid + l * 512;
        int cc = idx & 31;
        int k = idx >> 5;
        int col = ((cc >> 3) << 10) + u0 + (cc & 7);
        float v = W[(size_t)k * N4U + col];
        __nv_bfloat16 hi = __float2bfloat16(v);
        Whi[cc * WROW + k] = hi;
        Wlo[cc * WROW + k] = __float2bfloat16(v - __bfloat162float(hi));
    }

    // finisher cell: 1 per thread
    const int fb = tid >> 3;          // batch 0..63
    const int fu = tid & 7;           // unit within tile
    const float* xgp = g_xg + (size_t)fb * T_ * N4U + u0 + fu;
    float c_reg = 0.f;

    const int ra = wm * 16 + lq;
    const int kbase = kq * 256;
    float* Zsl = Zs + kq * 64 * 33;

    for (int t = 0; t < T_; t++) {
        gridbar2(t);   // all h[t&1] writes visible; covers W-load at t=0

        // prefetch this step's x-gate values (independent of h)
        float xg0 = xgp[(size_t)t * N4U];
        float xg1 = xgp[(size_t)t * N4U + (1 << 10)];
        float xg2 = xgp[(size_t)t * N4U + (2 << 10)];
        float xg3 = xgp[(size_t)t * N4U + (3 << 10)];

        const __nv_bfloat16* __restrict__ hh = g_hhi[t & 1];
        const __nv_bfloat16* __restrict__ hl = g_hlo[t & 1];

        float acc[4][4];
        #pragma unroll
        for (int j = 0; j < 4; j++)
            #pragma unroll
            for (int q = 0; q < 4; q++) acc[j][q] = 0.f;

        #pragma unroll 4
        for (int s = 0; s < 16; s++) {
            const int k = kbase + s * 16;
            const __nv_bfloat16* p0 = hh + ra * U_ + k;
            const __nv_bfloat16* p1 = hh + (ra + 8) * U_ + k;
            const __nv_bfloat16* q0 = hl + ra * U_ + k;
            const __nv_bfloat16* q1 = hl + (ra + 8) * U_ + k;
            uint32_t ahi[4], alo[4];
            ahi[0] = *(const uint32_t*)(p0 + lr);
            ahi[1] = *(const uint32_t*)(p1 + lr);
            ahi[2] = *(const uint32_t*)(p0 + 8 + lr);
            ahi[3] = *(const uint32_t*)(p1 + 8 + lr);
            alo[0] = *(const uint32_t*)(q0 + lr);
            alo[1] = *(const uint32_t*)(q1 + lr);
            alo[2] = *(const uint32_t*)(q0 + 8 + lr);
            alo[3] = *(const uint32_t*)(q1 + 8 + lr);
            #pragma unroll
            for (int j = 0; j < 4; j++) {
                const __nv_bfloat16* wh = Whi + (j * 8 + lq) * WROW + k;
                const __nv_bfloat16* wl = Wlo + (j * 8 + lq) * WROW + k;
                uint32_t bh[2], bl[2];
                bh[0] = *(const uint32_t*)(wh + lr);
                bh[1] = *(const uint32_t*)(wh + 8 + lr);
                bl[0] = *(const uint32_t*)(wl + lr);
                bl[1] = *(const uint32_t*)(wl + 8 + lr);
                MMA16816(acc[j], ahi, bh);
                MMA16816(acc[j], ahi, bl);
                MMA16816(acc[j], alo, bh);
            }
        }

        // ---- each kq writes its Zs slice ----
        #pragma unroll
        for (int j = 0; j < 4; j++) {
            int cgl = j * 8 + lr;
            Zsl[ra * 33 + cgl]           = acc[j][0];
            Zsl[ra * 33 + cgl + 1]       = acc[j][1];
            Zsl[(ra + 8) * 33 + cgl]     = acc[j][2];
            Zsl[(ra + 8) * 33 + cgl + 1] = acc[j][3];
        }
        __syncthreads();

        // ---- finisher: 1 cell per thread; fixed-order kq sum ----
        __nv_bfloat16* __restrict__ nhh = g_hhi[(t + 1) & 1];
        __nv_bfloat16* __restrict__ nhl = g_hlo[(t + 1) & 1];
        {
            float z[4] = {xg0, xg1, xg2, xg3};
            #pragma unroll
            for (int g = 0; g < 4; g++) {
                float s = 0.f;
                #pragma unroll
                for (int p = 0; p < 4; p++)
                    s += Zs[p * 64 * 33 + fb * 33 + g * 8 + fu];
                z[g] += s;
            }
            float iv = 1.f / (1.f + __expf(-z[0]));
            float fv = 1.f / (1.f + __expf(-z[1]));
            float gv = tanhf(z[2]);
            float ov = 1.f / (1.f + __expf(-z[3]));
            c_reg = fv * c_reg + iv * gv;
            float hv = ov * tanhf(c_reg);
            int hix = fb * U_ + u0 + fu;
            __nv_bfloat16 hi = __float2bfloat16(hv);
            nhh[hix] = hi;
            nhl[hix] = __float2bfloat16(hv - __bfloat162float(hi));
            if (t == T_ - 1) out[hix] = hv;
        }
        // next iteration's gridbar2 orders Zs reuse and h visibility
    }
}

// ---------------- launch --------------------------------------------------------
extern "C" void kernel_launch(void* const* d_in, const int* in_sizes, int n_in,
                              void* d_out, int out_size) {
    const float* x    = (const float*)d_in[0];
    const float* kern = (const float*)d_in[1];
    const float* rec  = (const float*)d_in[2];
    float* out = (float*)d_out;

    static int attr_done = 0;
    const size_t smem2 = (size_t)(32 * WROW * 2) * sizeof(__nv_bfloat16)
                       + (size_t)(4 * 64 * 33) * sizeof(float);   // ~166 KB
    if (!attr_done) {
        cudaFuncSetAttribute(lstm_persist_mma,
                             cudaFuncAttributeMaxDynamicSharedMemorySize, (int)smem2);
        cudaFuncSetAttribute(lstm_persist_mma,
                             cudaFuncAttributePreferredSharedMemoryCarveout, 100);
        attr_done = 1;
    }

    lstm_init<<<(B_ * U_ + 255) / 256, 256>>>();

    conv_x<<<(int)(((size_t)BT_ * D_ + 255) / 256), 256>>>(x);
    conv_w<<<(int)(((size_t)N4U * D_ + 255) / 256), 256>>>(kern);

    dim3 xg(N4U / 128, BT_ / 128);   // (32, 256)
    lstm_xgemm_mma<<<xg, 256>>>();

    lstm_persist_mma<<<NB2, 512, smem2>>>(rec, out);
}

// round 9
// speedup vs baseline: 2.8832x; 1.2438x over previous
#include <cuda_runtime.h>
#include <cuda_bf16.h>
#include <math.h>
#include <stdint.h>

typedef unsigned long long u64;

// Problem dims
#define B_ 64
#define T_ 512
#define D_ 512
#define U_ 1024
#define N4U 4096        // 4*U
#define BT_ (B_ * T_)   // 32768

#define NB2 128         // persistent blocks (1 per SM)

// mma.sync m16n8k16 bf16 (base PTX, works on compute_103) --------------------
#define MMA16816(c, a, b) \
    asm volatile("mma.sync.aligned.m16n8k16.row.col.f32.bf16.bf16.f32 " \
        "{%0,%1,%2,%3}, {%4,%5,%6,%7}, {%8,%9}, {%0,%1,%2,%3};" \
        : "+f"((c)[0]), "+f"((c)[1]), "+f"((c)[2]), "+f"((c)[3]) \
        : "r"((a)[0]), "r"((a)[1]), "r"((a)[2]), "r"((a)[3]), \
          "r"((b)[0]), "r"((b)[1]))

// ---------------- scratch (device globals) ----------------------------------
__device__ float g_xg[(size_t)BT_ * N4U];             // [B*T, 4U]
// h in MMA-fragment-major order: tile=(kq*16+s)*4+wm, then lane*8 + reg*2 + elem
__device__ __nv_bfloat16 g_hhiP[2][B_ * U_];
__device__ __nv_bfloat16 g_hloP[2][B_ * U_];
__device__ unsigned g_bar2[T_];
__device__ __nv_bfloat16 g_xhi[(size_t)BT_ * D_];
__device__ __nv_bfloat16 g_xlo[(size_t)BT_ * D_];
__device__ __nv_bfloat16 g_whi[(size_t)N4U * D_];     // x-proj W^T: [n][k]
__device__ __nv_bfloat16 g_wlo[(size_t)N4U * D_];

// ---------------- init -------------------------------------------------------
__global__ void lstm_init() {
    int i = blockIdx.x * blockDim.x + threadIdx.x;
    if (i < B_ * U_) {
        g_hhiP[0][i] = __float2bfloat16(0.f);
        g_hloP[0][i] = __float2bfloat16(0.f);
    }
    if (i < T_) g_bar2[i] = 0u;
}

// ---------------- split-precision converters ---------------------------------
__global__ void conv_x(const float* __restrict__ x) {
    size_t i = (size_t)blockIdx.x * blockDim.x + threadIdx.x;
    if (i >= (size_t)BT_ * D_) return;
    float v = x[i];
    __nv_bfloat16 hi = __float2bfloat16(v);
    __nv_bfloat16 lo = __float2bfloat16(v - __bfloat162float(hi));
    g_xhi[i] = hi; g_xlo[i] = lo;
}
__global__ void conv_w(const float* __restrict__ W) {
    size_t i = (size_t)blockIdx.x * blockDim.x + threadIdx.x;  // over n*512+k
    if (i >= (size_t)N4U * D_) return;
    int n = (int)(i >> 9);
    int k = (int)(i & 511);
    float v = W[(size_t)k * N4U + n];
    __nv_bfloat16 hi = __float2bfloat16(v);
    __nv_bfloat16 lo = __float2bfloat16(v - __bfloat162float(hi));
    g_whi[i] = hi; g_wlo[i] = lo;
}

// ---------------- mma.sync xgemm: g_xg = x @ kernel (bf16x3 split) -------------
__global__ __launch_bounds__(256, 1)
void lstm_xgemm_mma() {
    __shared__ __nv_bfloat16 Ahi[128][40];
    __shared__ __nv_bfloat16 Alo[128][40];
    __shared__ __nv_bfloat16 Bhi[128][40];
    __shared__ __nv_bfloat16 Blo[128][40];

    const int tid = threadIdx.x;
    const int wid = tid >> 5;
    const int lane = tid & 31;
    const int wm = wid & 1;
    const int wn = wid >> 1;
    const int m0 = blockIdx.y * 128;
    const int n0 = blockIdx.x * 128;
    const int lq = lane >> 2;
    const int lr = (lane & 3) << 1;

    float acc[4][4][4];
    #pragma unroll
    for (int i = 0; i < 4; i++)
        #pragma unroll
        for (int j = 0; j < 4; j++)
            #pragma unroll
            for (int q = 0; q < 4; q++) acc[i][j][q] = 0.f;

    for (int kc = 0; kc < 16; kc++) {
        const int k0 = kc * 32;
        #pragma unroll
        for (int l = 0; l < 4; l++) {
            int i = tid + l * 256;
            int r = i >> 3;
            int c4 = (i & 7) << 2;
            size_t ga = (size_t)(m0 + r) * D_ + k0 + c4;
            *(uint2*)&Ahi[r][c4] = *(const uint2*)(g_xhi + ga);
            *(uint2*)&Alo[r][c4] = *(const uint2*)(g_xlo + ga);
            size_t gb = (size_t)(n0 + r) * D_ + k0 + c4;
            *(uint2*)&Bhi[r][c4] = *(const uint2*)(g_whi + gb);
            *(uint2*)&Blo[r][c4] = *(const uint2*)(g_wlo + gb);
        }
        __syncthreads();

        #pragma unroll
        for (int ksi = 0; ksi < 2; ksi++) {
            const int k16 = ksi * 16;
            uint32_t ahi[4][4], alo[4][4], bhi[4][2], blo[4][2];
            #pragma unroll
            for (int i = 0; i < 4; i++) {
                int r = wm * 64 + i * 16 + lq;
                ahi[i][0] = *(uint32_t*)&Ahi[r][k16 + lr];
                ahi[i][1] = *(uint32_t*)&Ahi[r + 8][k16 + lr];
                ahi[i][2] = *(uint32_t*)&Ahi[r][k16 + lr + 8];
                ahi[i][3] = *(uint32_t*)&Ahi[r + 8][k16 + lr + 8];
                alo[i][0] = *(uint32_t*)&Alo[r][k16 + lr];
                alo[i][1] = *(uint32_t*)&Alo[r + 8][k16 + lr];
                alo[i][2] = *(uint32_t*)&Alo[r][k16 + lr + 8];
                alo[i][3] = *(uint32_t*)&Alo[r + 8][k16 + lr + 8];
            }
            #pragma unroll
            for (int j = 0; j < 4; j++) {
                int r = wn * 32 + j * 8 + lq;
                bhi[j][0] = *(uint32_t*)&Bhi[r][k16 + lr];
                bhi[j][1] = *(uint32_t*)&Bhi[r][k16 + lr + 8];
                blo[j][0] = *(uint32_t*)&Blo[r][k16 + lr];
                blo[j][1] = *(uint32_t*)&Blo[r][k16 + lr + 8];
            }
            #pragma unroll
            for (int i = 0; i < 4; i++)
                #pragma unroll
                for (int j = 0; j < 4; j++) {
                    MMA16816(acc[i][j], ahi[i], bhi[j]);
                    MMA16816(acc[i][j], ahi[i], blo[j]);
                    MMA16816(acc[i][j], alo[i], bhi[j]);
                }
        }
        __syncthreads();
    }

    #pragma unroll
    for (int i = 0; i < 4; i++) {
        int row = m0 + wm * 64 + i * 16 + lq;
        #pragma unroll
        for (int j = 0; j < 4; j++) {
            int col = n0 + wn * 32 + j * 8 + lr;
            *(float2*)&g_xg[(size_t)row * N4U + col] =
                make_float2(acc[i][j][0], acc[i][j][1]);
            *(float2*)&g_xg[(size_t)(row + 8) * N4U + col] =
                make_float2(acc[i][j][2], acc[i][j][3]);
        }
    }
}

// ---------------- grid-wide barrier (128 blocks) -------------------------------
__device__ __forceinline__ void gridbar2(int t) {
    __syncthreads();
    if (threadIdx.x == 0) {
        __threadfence();
        atomicAdd(&g_bar2[t], 1u);
        while (((volatile unsigned*)g_bar2)[t] < (unsigned)NB2) __nanosleep(32);
    }
    __syncthreads();
    __threadfence();
}

// ---------------- persistent recurrent LSTM (fragment-major operands) ----------
// 128 blocks x 512 thr. Block owns 8 units (32 z-cols), K=1024.
// Warps: wm = wid&3 (batch m16-tile), kq = wid>>2 (K-quarter of 256).
// h gmem layout: tile=(kq*16+s)*4+wm -> 256 elems: lane*8 + reg*2 + elem.
//   Per k16 iter: A-hi = one LDG.128, A-lo = one LDG.128.
// W smem layout: tile2=((kq*16+s)*4+j) -> 32 lanes x 8 bf16 [bh0,bh1,bl0,bl1].
//   Per k16 iter per j: one LDS.128.
__global__ __launch_bounds__(512)
void lstm_persist_mma(const float* __restrict__ W, float* __restrict__ out) {
    extern __shared__ char sm2[];
    __nv_bfloat16* Wp = (__nv_bfloat16*)sm2;         // 65536 bf16 = 128 KB
    float* Zs = (float*)(Wp + 65536);                // [4][64][33]

    const int tid = threadIdx.x;
    const int wid = tid >> 5;
    const int lane = tid & 31;
    const int wm = wid & 3;
    const int kq = wid >> 2;          // 0..3
    const int u0 = blockIdx.x * 8;
    const int lq = lane >> 2;
    const int lr = (lane & 3) << 1;

    // ---- load + split + permute W tile into smem (once): 32 cols x 1024 k ----
    for (int l = 0; l < 64; l++) {
        int idx = tid + l * 512;
        int cc = idx & 31;            // 0..31 (j = cc>>3 = gate, n = cc&7)
        int k = idx >> 5;             // 0..1023
        int col = ((cc >> 3) << 10) + u0 + (cc & 7);
        float v = W[(size_t)k * N4U + col];
        __nv_bfloat16 hi = __float2bfloat16(v);
        __nv_bfloat16 lo = __float2bfloat16(v - __bfloat162float(hi));
        int kqi = k >> 8, si = (k >> 4) & 15, kk = k & 15;
        int j = cc >> 3, n = cc & 7;
        int ln = n * 4 + ((kk >> 1) & 3);
        int reg = kk >> 3, elem = kk & 1;
        int base = (((kqi * 16 + si) * 4 + j) * 32 + ln) * 8;
        Wp[base + reg * 2 + elem] = hi;
        Wp[base + 4 + reg * 2 + elem] = lo;
    }

    // ---- finisher cell: 1 per thread; precompute permuted h write addr ----
    const int fb = tid >> 3;          // batch 0..63
    const int fu = tid & 7;           // unit within tile
    const int ug = u0 + fu;           // global unit = h column
    const float* xgp = g_xg + (size_t)fb * T_ * N4U + ug;
    float c_reg = 0.f;
    int paddr;
    {
        int r = fb & 15, wmw = fb >> 4;
        int kqw = ug >> 8, sw = (ug >> 4) & 15, cw = ug & 15;
        int lnw = (r & 7) * 4 + ((cw >> 1) & 3);
        int regw = (r >> 3) | ((cw >> 3) << 1);
        paddr = (((kqw * 16 + sw) * 4 + wmw) * 256) + lnw * 8 + regw * 2 + (cw & 1);
    }

    float* Zsl = Zs + kq * 64 * 33;
    const int ra = wm * 16 + lq;
    const int tbase = (kq * 16) * 4 + wm;   // tile id at s=0

    for (int t = 0; t < T_; t++) {
        gridbar2(t);   // all h[t&1] writes visible; covers W-load at t=0

        // prefetch this step's x-gate values (independent of h)
        float xg0 = xgp[(size_t)t * N4U];
        float xg1 = xgp[(size_t)t * N4U + (1 << 10)];
        float xg2 = xgp[(size_t)t * N4U + (2 << 10)];
        float xg3 = xgp[(size_t)t * N4U + (3 << 10)];

        const __nv_bfloat16* __restrict__ hh = g_hhiP[t & 1];
        const __nv_bfloat16* __restrict__ hl = g_hloP[t & 1];

        float acc[4][4];
        #pragma unroll
        for (int j = 0; j < 4; j++)
            #pragma unroll
            for (int q = 0; q < 4; q++) acc[j][q] = 0.f;

        #pragma unroll 4
        for (int s = 0; s < 16; s++) {
            const int off = (tbase + s * 4) * 256 + lane * 8;
            uint4 Ah = *(const uint4*)(hh + off);
            uint4 Al = *(const uint4*)(hl + off);
            const uint32_t* ahi = (const uint32_t*)&Ah;
            const uint32_t* alo = (const uint32_t*)&Al;
            #pragma unroll
            for (int j = 0; j < 4; j++) {
                uint4 wv = *(const uint4*)(Wp + (((kq * 16 + s) * 4 + j) * 32 + lane) * 8);
                uint32_t bh[2] = {wv.x, wv.y};
                uint32_t bl[2] = {wv.z, wv.w};
                MMA16816(acc[j], ahi, bh);
                MMA16816(acc[j], ahi, bl);
                MMA16816(acc[j], alo, bh);
            }
        }

        // ---- each kq writes its Zs slice ----
        #pragma unroll
        for (int j = 0; j < 4; j++) {
            int cgl = j * 8 + lr;
            Zsl[ra * 33 + cgl]           = acc[j][0];
            Zsl[ra * 33 + cgl + 1]       = acc[j][1];
            Zsl[(ra + 8) * 33 + cgl]     = acc[j][2];
            Zsl[(ra + 8) * 33 + cgl + 1] = acc[j][3];
        }
        __syncthreads();

        // ---- finisher: 1 cell per thread; fixed-order kq sum ----
        __nv_bfloat16* __restrict__ nhh = g_hhiP[(t + 1) & 1];
        __nv_bfloat16* __restrict__ nhl = g_hloP[(t + 1) & 1];
        {
            float z[4] = {xg0, xg1, xg2, xg3};
            #pragma unroll
            for (int g = 0; g < 4; g++) {
                float s = 0.f;
                #pragma unroll
                for (int p = 0; p < 4; p++)
                    s += Zs[p * 64 * 33 + fb * 33 + g * 8 + fu];
                z[g] += s;
            }
            float iv = 1.f / (1.f + __expf(-z[0]));
            float fv = 1.f / (1.f + __expf(-z[1]));
            float gv = tanhf(z[2]);
            float ov = 1.f / (1.f + __expf(-z[3]));
            c_reg = fv * c_reg + iv * gv;
            float hv = ov * tanhf(c_reg);
            __nv_bfloat16 hi = __float2bfloat16(hv);
            nhh[paddr] = hi;
            nhl[paddr] = __float2bfloat16(hv - __bfloat162float(hi));
            if (t == T_ - 1) out[fb * U_ + ug] = hv;
        }
        // next iteration's gridbar2 orders Zs reuse and h visibility
    }
}

// ---------------- launch --------------------------------------------------------
extern "C" void kernel_launch(void* const* d_in, const int* in_sizes, int n_in,
                              void* d_out, int out_size) {
    const float* x    = (const float*)d_in[0];
    const float* kern = (const float*)d_in[1];
    const float* rec  = (const float*)d_in[2];
    float* out = (float*)d_out;

    static int attr_done = 0;
    const size_t smem2 = (size_t)65536 * sizeof(__nv_bfloat16)
                       + (size_t)(4 * 64 * 33) * sizeof(float);   // ~162 KB
    if (!attr_done) {
        cudaFuncSetAttribute(lstm_persist_mma,
                             cudaFuncAttributeMaxDynamicSharedMemorySize, (int)smem2);
        cudaFuncSetAttribute(lstm_persist_mma,
                             cudaFuncAttributePreferredSharedMemoryCarveout, 100);
        attr_done = 1;
    }

    lstm_init<<<(B_ * U_ + 255) / 256, 256>>>();

    conv_x<<<(int)(((size_t)BT_ * D_ + 255) / 256), 256>>>(x);
    conv_w<<<(int)(((size_t)N4U * D_ + 255) / 256), 256>>>(kern);

    dim3 xg(N4U / 128, BT_ / 128);   // (32, 256)
    lstm_xgemm_mma<<<xg, 256>>>();

    lstm_persist_mma<<<NB2, 512, smem2>>>(rec, out);
}